// round 4
// baseline (speedup 1.0000x reference)
#include <cuda_runtime.h>
#include <cuda_bf16.h>
#include <cstdint>

// ---------------- problem constants (fixed by dataset) ----------------
#define NNODES 100000
#define NEDGES 1600000
#define DH 128           // feature dim (D == H)
#define NG 512           // num graphs
#define NL 5             // total reps (input + 4 layers)
#define NLG 4            // GIN layers
#define OO 64            // output dim
#define BN_EPS 1e-5f

// ---------------- static device scratch (no allocations allowed) ------
__device__ float g_zl[NLG][(size_t)NNODES * DH];      // z per GIN layer
__device__ float g_y1[(size_t)NNODES * DH];
__device__ int   g_deg[NNODES];
__device__ int   g_off[NNODES + 1];
__device__ int   g_cursor[NNODES];
__device__ int   g_srcs[NEDGES];
__device__ int   g_gstart[NG + 1];
__device__ float g_stats[NLG][2][2 * DH];   // [layer][stage][sum(128)|sumsq(128)]
__device__ float g_ph[NL][NG * DH];         // per-graph pooled reps
// bf16 hi/lo split weights, transposed to [n][k]: mats 0..3 = W1[l], 4..7 = W2[l]
__device__ __nv_bfloat16 g_whi[8][DH * DH];
__device__ __nv_bfloat16 g_wlo[8][DH * DH];

// ---------------- helpers ----------------------------------------------
__device__ __forceinline__ uint32_t smem_u32(const void* p) {
    uint32_t a;
    asm("{ .reg .u64 t; cvta.to.shared.u64 t, %1; cvt.u32.u64 %0, t; }"
        : "=r"(a) : "l"(p));
    return a;
}

__device__ __forceinline__ void ldx4(uint32_t* r, uint32_t addr) {
    asm volatile("ldmatrix.sync.aligned.m8n8.x4.shared.b16 {%0,%1,%2,%3}, [%4];"
                 : "=r"(r[0]), "=r"(r[1]), "=r"(r[2]), "=r"(r[3]) : "r"(addr));
}

__device__ __forceinline__ void mma16816(float* c, const uint32_t* a,
                                         uint32_t b0, uint32_t b1) {
    asm volatile(
        "mma.sync.aligned.m16n8k16.row.col.f32.bf16.bf16.f32 "
        "{%0,%1,%2,%3}, {%4,%5,%6,%7}, {%8,%9}, {%0,%1,%2,%3};"
        : "+f"(c[0]), "+f"(c[1]), "+f"(c[2]), "+f"(c[3])
        : "r"(a[0]), "r"(a[1]), "r"(a[2]), "r"(a[3]), "r"(b0), "r"(b1));
}

// smem tile geometry: 128 rows x 136 bf16 (272B rows -> conflict-free ldmatrix)
#define LDT 136
#define TILE_B (128 * LDT * 2)           // 34816 bytes per matrix
#define SMEM_BYTES (4 * TILE_B + 4 * 128 * 4)

// ---------------- small utility kernels --------------------------------
__global__ void zero_kernel(int n_nodes) {
    int i = blockIdx.x * blockDim.x + threadIdx.x;
    if (i < n_nodes) g_deg[i] = 0;
    if (i < NLG * 2 * 2 * DH) ((float*)g_stats)[i] = 0.0f;
}

__global__ void hist_kernel(const int* __restrict__ dst, int E) {
    int i = blockIdx.x * blockDim.x + threadIdx.x;
    if (i < E) atomicAdd(&g_deg[dst[i]], 1);
}

__global__ void scan_kernel(int n) {
    __shared__ int warpsum[32];
    __shared__ int carry_s;
    int tid = threadIdx.x, lane = tid & 31, wid = tid >> 5;
    if (tid == 0) carry_s = 0;
    __syncthreads();
    for (int base = 0; base < n; base += 1024) {
        int i = base + tid;
        int v = (i < n) ? g_deg[i] : 0;
        int xv = v;
        #pragma unroll
        for (int o = 1; o < 32; o <<= 1) {
            int t = __shfl_up_sync(0xffffffffu, xv, o);
            if (lane >= o) xv += t;
        }
        if (lane == 31) warpsum[wid] = xv;
        __syncthreads();
        if (wid == 0) {
            int w = warpsum[lane];
            int yv = w;
            #pragma unroll
            for (int o = 1; o < 32; o <<= 1) {
                int t = __shfl_up_sync(0xffffffffu, yv, o);
                if (lane >= o) yv += t;
            }
            warpsum[lane] = yv - w;
        }
        __syncthreads();
        int excl = carry_s + warpsum[wid] + xv - v;
        if (i < n) { g_off[i] = excl; g_cursor[i] = excl; }
        __syncthreads();
        if (tid == 1023) carry_s += warpsum[31] + xv;
        __syncthreads();
    }
    if (tid == 0) g_off[n] = carry_s;
}

__global__ void scatter_kernel(const int* __restrict__ src,
                               const int* __restrict__ dst, int E) {
    int i = blockIdx.x * blockDim.x + threadIdx.x;
    if (i < E) {
        int p = atomicAdd(&g_cursor[dst[i]], 1);
        g_srcs[p] = src[i];
    }
}

__global__ void gbounds_kernel(const int* __restrict__ gid, int n) {
    int i = blockIdx.x * blockDim.x + threadIdx.x;
    if (i > n) return;
    if (i == 0) {
        int b = gid[0];
        for (int g = 0; g <= b; ++g) g_gstart[g] = 0;
    } else if (i == n) {
        int a = gid[n - 1];
        for (int g = a + 1; g <= NG; ++g) g_gstart[g] = n;
    } else {
        int a = gid[i - 1], b = gid[i];
        for (int g = a + 1; g <= b; ++g) g_gstart[g] = i;
    }
}

// weight convert: W[k][n] fp32 -> [n][k] bf16 hi/lo (mats 0-3: W1, 4-7: W2)
__global__ void wconv_kernel(const float* __restrict__ W1,
                             const float* __restrict__ W2) {
    int i = blockIdx.x * blockDim.x + threadIdx.x;
    if (i >= 8 * DH * DH) return;
    int mat = i >> 14, r = i & 16383;
    int n = r >> 7, k = r & 127;
    const float* src = (mat < 4) ? (W1 + ((size_t)mat << 14))
                                 : (W2 + ((size_t)(mat - 4) << 14));
    float v = src[k * DH + n];
    __nv_bfloat16 hi = __float2bfloat16(v);
    __nv_bfloat16 lo = __float2bfloat16(v - __bfloat162float(hi));
    g_whi[mat][r] = hi;
    g_wlo[mat][r] = lo;
}

// ---------------- fused gather + GEMM1 ---------------------------------
// pooled = agg(f(Hsrc)) + (1+eps) f(Hsrc_self), f = identity (FIRST) or
// relu(affine) with the previous layer's outer-BN params.
// Then y1 = pooled @ W1^T + b1 via 3-term bf16-split mma; stage-0 stats.
template <bool FIRST>
__global__ void __launch_bounds__(512)
fused_agg_gemm1(const float* __restrict__ Hsrc,
                const __nv_bfloat16* __restrict__ Bhi,
                const __nv_bfloat16* __restrict__ Blo,
                const float* __restrict__ bias,
                const float* __restrict__ go_prev,
                const float* __restrict__ bo_prev,
                const float* __restrict__ eps,
                float* __restrict__ C, int l, int M) {
    extern __shared__ char sb[];
    __nv_bfloat16* sAhi = (__nv_bfloat16*)sb;
    __nv_bfloat16* sAlo = sAhi + 128 * LDT;
    __nv_bfloat16* sBhi = sAlo + 128 * LDT;
    __nv_bfloat16* sBlo = sBhi + 128 * LDT;
    float* s_pscale = (float*)(sBlo + 128 * LDT);
    float* s_pshift = s_pscale + 128;
    float* s_sum    = s_pshift + 128;
    float* s_sq     = s_sum + 128;

    int tid = threadIdx.x;
    if (tid < 128) { s_sum[tid] = 0.0f; s_sq[tid] = 0.0f; }
    if (!FIRST && tid < 128) {
        float inv = 1.0f / (float)M;
        float m = g_stats[l - 1][1][tid] * inv;
        float v = g_stats[l - 1][1][128 + tid] * inv - m * m;
        float s = __ldg(&go_prev[tid]) * rsqrtf(v + BN_EPS);
        s_pscale[tid] = s;
        s_pshift[tid] = __ldg(&bo_prev[tid]) - m * s;
    }

    // ---- stage B hi/lo ([n][k] bf16) into smem ----
    const uint32_t* bh = (const uint32_t*)Bhi;
    const uint32_t* bl = (const uint32_t*)Blo;
    #pragma unroll
    for (int it = 0; it < 16; ++it) {
        int i = tid + it * 512;              // 8192 u32
        int n = i >> 6, kp = (i & 63);
        int d = n * LDT + kp * 2;
        *(uint32_t*)&sBhi[d] = bh[i];
        *(uint32_t*)&sBlo[d] = bl[i];
    }
    __syncthreads();   // s_pscale/s_pshift ready

    // ---- gather: warp handles 8 consecutive nodes, lane = 4 columns ----
    int w = tid >> 5, lane = tid & 31;
    int row0 = blockIdx.x * 128;
    float4 sc = make_float4(1.f, 1.f, 1.f, 1.f);
    float4 sh = make_float4(0.f, 0.f, 0.f, 0.f);
    if (!FIRST) {
        sc = *(float4*)&s_pscale[lane * 4];
        sh = *(float4*)&s_pshift[lane * 4];
    }
    float onepe = 1.0f + __ldg(&eps[l]);
    const float4* hv = (const float4*)Hsrc;

    #pragma unroll
    for (int i = 0; i < 8; ++i) {
        int rloc = w * 8 + i;
        int node = row0 + rloc;
        float4 acc = make_float4(0.f, 0.f, 0.f, 0.f);
        if (node < M) {
            float4 v = __ldg(&hv[(size_t)node * 32 + lane]);
            if (!FIRST) {
                v.x = fmaxf(fmaf(v.x, sc.x, sh.x), 0.0f);
                v.y = fmaxf(fmaf(v.y, sc.y, sh.y), 0.0f);
                v.z = fmaxf(fmaf(v.z, sc.z, sh.z), 0.0f);
                v.w = fmaxf(fmaf(v.w, sc.w, sh.w), 0.0f);
            }
            acc.x = onepe * v.x; acc.y = onepe * v.y;
            acc.z = onepe * v.z; acc.w = onepe * v.w;
            int s = g_off[node], e = g_off[node + 1];
            int j = s;
            for (; j + 4 <= e; j += 4) {
                int s0 = g_srcs[j], s1 = g_srcs[j + 1];
                int s2 = g_srcs[j + 2], s3 = g_srcs[j + 3];
                float4 v0 = __ldg(&hv[(size_t)s0 * 32 + lane]);
                float4 v1 = __ldg(&hv[(size_t)s1 * 32 + lane]);
                float4 v2 = __ldg(&hv[(size_t)s2 * 32 + lane]);
                float4 v3 = __ldg(&hv[(size_t)s3 * 32 + lane]);
                if (!FIRST) {
                    v0.x = fmaxf(fmaf(v0.x, sc.x, sh.x), 0.0f);
                    v0.y = fmaxf(fmaf(v0.y, sc.y, sh.y), 0.0f);
                    v0.z = fmaxf(fmaf(v0.z, sc.z, sh.z), 0.0f);
                    v0.w = fmaxf(fmaf(v0.w, sc.w, sh.w), 0.0f);
                    v1.x = fmaxf(fmaf(v1.x, sc.x, sh.x), 0.0f);
                    v1.y = fmaxf(fmaf(v1.y, sc.y, sh.y), 0.0f);
                    v1.z = fmaxf(fmaf(v1.z, sc.z, sh.z), 0.0f);
                    v1.w = fmaxf(fmaf(v1.w, sc.w, sh.w), 0.0f);
                    v2.x = fmaxf(fmaf(v2.x, sc.x, sh.x), 0.0f);
                    v2.y = fmaxf(fmaf(v2.y, sc.y, sh.y), 0.0f);
                    v2.z = fmaxf(fmaf(v2.z, sc.z, sh.z), 0.0f);
                    v2.w = fmaxf(fmaf(v2.w, sc.w, sh.w), 0.0f);
                    v3.x = fmaxf(fmaf(v3.x, sc.x, sh.x), 0.0f);
                    v3.y = fmaxf(fmaf(v3.y, sc.y, sh.y), 0.0f);
                    v3.z = fmaxf(fmaf(v3.z, sc.z, sh.z), 0.0f);
                    v3.w = fmaxf(fmaf(v3.w, sc.w, sh.w), 0.0f);
                }
                acc.x += (v0.x + v1.x) + (v2.x + v3.x);
                acc.y += (v0.y + v1.y) + (v2.y + v3.y);
                acc.z += (v0.z + v1.z) + (v2.z + v3.z);
                acc.w += (v0.w + v1.w) + (v2.w + v3.w);
            }
            for (; j < e; ++j) {
                float4 v0 = __ldg(&hv[(size_t)g_srcs[j] * 32 + lane]);
                if (!FIRST) {
                    v0.x = fmaxf(fmaf(v0.x, sc.x, sh.x), 0.0f);
                    v0.y = fmaxf(fmaf(v0.y, sc.y, sh.y), 0.0f);
                    v0.z = fmaxf(fmaf(v0.z, sc.z, sh.z), 0.0f);
                    v0.w = fmaxf(fmaf(v0.w, sc.w, sh.w), 0.0f);
                }
                acc.x += v0.x; acc.y += v0.y; acc.z += v0.z; acc.w += v0.w;
            }
        }
        // convert to bf16 hi/lo, write A tile
        __nv_bfloat16 hx = __float2bfloat16(acc.x), hy = __float2bfloat16(acc.y);
        __nv_bfloat16 hz = __float2bfloat16(acc.z), hw = __float2bfloat16(acc.w);
        uint2 hi2, lo2;
        {
            __nv_bfloat162 t01, t23;
            t01.x = hx; t01.y = hy; t23.x = hz; t23.y = hw;
            hi2.x = *(uint32_t*)&t01; hi2.y = *(uint32_t*)&t23;
            t01.x = __float2bfloat16(acc.x - __bfloat162float(hx));
            t01.y = __float2bfloat16(acc.y - __bfloat162float(hy));
            t23.x = __float2bfloat16(acc.z - __bfloat162float(hz));
            t23.y = __float2bfloat16(acc.w - __bfloat162float(hw));
            lo2.x = *(uint32_t*)&t01; lo2.y = *(uint32_t*)&t23;
        }
        int d = rloc * LDT + lane * 4;
        *(uint2*)&sAhi[d] = hi2;
        *(uint2*)&sAlo[d] = lo2;
    }
    __syncthreads();

    // ---- warp-tile mma: 4x4 warps, each 32(m) x 32(n) ----
    int mw = (w >> 2) * 32, nw = (w & 3) * 32;
    uint32_t base = smem_u32(sb);
    uint32_t aoff = ((mw + (lane & 15)) * LDT + ((lane >> 4) * 8)) * 2;
    uint32_t boff = ((nw + (lane & 7) + ((lane >> 4) << 3)) * LDT
                     + (((lane >> 3) & 1) * 8)) * 2;

    float acc[2][4][4];
    #pragma unroll
    for (int i = 0; i < 2; ++i)
        #pragma unroll
        for (int j = 0; j < 4; ++j)
            #pragma unroll
            for (int k = 0; k < 4; ++k) acc[i][j][k] = 0.0f;

    const uint32_t aT[3] = {0u, (uint32_t)TILE_B, 0u};
    const uint32_t bT[3] = {2u * TILE_B, 2u * TILE_B, 3u * TILE_B};
    #pragma unroll
    for (int t = 0; t < 3; ++t) {
        uint32_t ab = base + aT[t] + aoff;
        uint32_t bb = base + bT[t] + boff;
        #pragma unroll
        for (int ks = 0; ks < 8; ++ks) {
            uint32_t a0[4], a1[4], b0[4], b1[4];
            ldx4(a0, ab + ks * 32);
            ldx4(a1, ab + 16 * LDT * 2 + ks * 32);
            ldx4(b0, bb + ks * 32);
            ldx4(b1, bb + 16 * LDT * 2 + ks * 32);
            mma16816(acc[0][0], a0, b0[0], b0[1]);
            mma16816(acc[0][1], a0, b0[2], b0[3]);
            mma16816(acc[0][2], a0, b1[0], b1[1]);
            mma16816(acc[0][3], a0, b1[2], b1[3]);
            mma16816(acc[1][0], a1, b0[0], b0[1]);
            mma16816(acc[1][1], a1, b0[2], b0[3]);
            mma16816(acc[1][2], a1, b1[0], b1[1]);
            mma16816(acc[1][3], a1, b1[2], b1[3]);
        }
    }

    // ---- epilogue: bias, direct store, column stats (stage 0) ----
    float csum[8], csq[8];
    #pragma unroll
    for (int i = 0; i < 8; ++i) { csum[i] = 0.0f; csq[i] = 0.0f; }
    #pragma unroll
    for (int nf = 0; nf < 4; ++nf) {
        int col = nw + nf * 8 + (lane & 3) * 2;
        float bx = __ldg(&bias[col]), by = __ldg(&bias[col + 1]);
        #pragma unroll
        for (int mf = 0; mf < 2; ++mf) {
            int r0 = row0 + mw + mf * 16 + (lane >> 2);
            float v0 = acc[mf][nf][0] + bx, v1 = acc[mf][nf][1] + by;
            float v2 = acc[mf][nf][2] + bx, v3 = acc[mf][nf][3] + by;
            if (r0 < M) {
                *(float2*)&C[(size_t)r0 * DH + col] = make_float2(v0, v1);
                csum[nf * 2] += v0; csum[nf * 2 + 1] += v1;
                csq[nf * 2] += v0 * v0; csq[nf * 2 + 1] += v1 * v1;
            }
            if (r0 + 8 < M) {
                *(float2*)&C[(size_t)(r0 + 8) * DH + col] = make_float2(v2, v3);
                csum[nf * 2] += v2; csum[nf * 2 + 1] += v3;
                csq[nf * 2] += v2 * v2; csq[nf * 2 + 1] += v3 * v3;
            }
        }
    }
    #pragma unroll
    for (int nf = 0; nf < 4; ++nf) {
        int col = nw + nf * 8 + (lane & 3) * 2;
        atomicAdd(&s_sum[col], csum[nf * 2]);
        atomicAdd(&s_sum[col + 1], csum[nf * 2 + 1]);
        atomicAdd(&s_sq[col], csq[nf * 2]);
        atomicAdd(&s_sq[col + 1], csq[nf * 2 + 1]);
    }
    __syncthreads();
    if (tid < 128) {
        atomicAdd(&g_stats[l][0][tid], s_sum[tid]);
        atomicAdd(&g_stats[l][0][128 + tid], s_sq[tid]);
    }
}

// ---------------- GEMM2: z = relu(bn(y1)) @ W2^T + b2, stage-1 stats ----
__global__ void __launch_bounds__(512)
gemm2_mma(const float* __restrict__ A,
          const __nv_bfloat16* __restrict__ Bhi, const __nv_bfloat16* __restrict__ Blo,
          const float* __restrict__ bias,
          const float* __restrict__ gamma, const float* __restrict__ beta,
          float* __restrict__ C, int l, int M) {
    extern __shared__ char sb[];
    __nv_bfloat16* sAhi = (__nv_bfloat16*)sb;
    __nv_bfloat16* sAlo = sAhi + 128 * LDT;
    __nv_bfloat16* sBhi = sAlo + 128 * LDT;
    __nv_bfloat16* sBlo = sBhi + 128 * LDT;
    float* s_scale = (float*)(sBlo + 128 * LDT);
    float* s_shift = s_scale + 128;
    float* s_sum   = s_shift + 128;
    float* s_sq    = s_sum + 128;

    int tid = threadIdx.x;
    if (tid < 128) { s_sum[tid] = 0.0f; s_sq[tid] = 0.0f; }
    if (tid < 128) {
        float inv = 1.0f / (float)M;
        float m = g_stats[l][0][tid] * inv;
        float v = g_stats[l][0][128 + tid] * inv - m * m;
        float s = __ldg(&gamma[tid]) * rsqrtf(v + BN_EPS);
        s_scale[tid] = s;
        s_shift[tid] = __ldg(&beta[tid]) - m * s;
    }
    __syncthreads();

    const uint32_t* bh = (const uint32_t*)Bhi;
    const uint32_t* bl = (const uint32_t*)Blo;
    #pragma unroll
    for (int it = 0; it < 16; ++it) {
        int i = tid + it * 512;
        int n = i >> 6, kp = (i & 63);
        int d = n * LDT + kp * 2;
        *(uint32_t*)&sBhi[d] = bh[i];
        *(uint32_t*)&sBlo[d] = bl[i];
    }

    int row0 = blockIdx.x * 128;
    const float4* A4 = (const float4*)(A + (size_t)row0 * DH);
    #pragma unroll
    for (int it = 0; it < 8; ++it) {
        int idx = tid + it * 512;
        int r = idx >> 5, c4 = (idx & 31) * 4;
        float4 v = make_float4(0.f, 0.f, 0.f, 0.f);
        if (row0 + r < M) v = A4[idx];
        v.x = fmaxf(fmaf(v.x, s_scale[c4 + 0], s_shift[c4 + 0]), 0.0f);
        v.y = fmaxf(fmaf(v.y, s_scale[c4 + 1], s_shift[c4 + 1]), 0.0f);
        v.z = fmaxf(fmaf(v.z, s_scale[c4 + 2], s_shift[c4 + 2]), 0.0f);
        v.w = fmaxf(fmaf(v.w, s_scale[c4 + 3], s_shift[c4 + 3]), 0.0f);
        __nv_bfloat16 hx = __float2bfloat16(v.x), hy = __float2bfloat16(v.y);
        __nv_bfloat16 hz = __float2bfloat16(v.z), hw = __float2bfloat16(v.w);
        uint2 hi2, lo2;
        {
            __nv_bfloat162 t01, t23;
            t01.x = hx; t01.y = hy; t23.x = hz; t23.y = hw;
            hi2.x = *(uint32_t*)&t01; hi2.y = *(uint32_t*)&t23;
            t01.x = __float2bfloat16(v.x - __bfloat162float(hx));
            t01.y = __float2bfloat16(v.y - __bfloat162float(hy));
            t23.x = __float2bfloat16(v.z - __bfloat162float(hz));
            t23.y = __float2bfloat16(v.w - __bfloat162float(hw));
            lo2.x = *(uint32_t*)&t01; lo2.y = *(uint32_t*)&t23;
        }
        int d = r * LDT + c4;
        *(uint2*)&sAhi[d] = hi2;
        *(uint2*)&sAlo[d] = lo2;
    }
    __syncthreads();

    int w = tid >> 5, lane = tid & 31;
    int mw = (w >> 2) * 32, nw = (w & 3) * 32;
    uint32_t base = smem_u32(sb);
    uint32_t aoff = ((mw + (lane & 15)) * LDT + ((lane >> 4) * 8)) * 2;
    uint32_t boff = ((nw + (lane & 7) + ((lane >> 4) << 3)) * LDT
                     + (((lane >> 3) & 1) * 8)) * 2;

    float acc[2][4][4];
    #pragma unroll
    for (int i = 0; i < 2; ++i)
        #pragma unroll
        for (int j = 0; j < 4; ++j)
            #pragma unroll
            for (int k = 0; k < 4; ++k) acc[i][j][k] = 0.0f;

    const uint32_t aT[3] = {0u, (uint32_t)TILE_B, 0u};
    const uint32_t bT[3] = {2u * TILE_B, 2u * TILE_B, 3u * TILE_B};
    #pragma unroll
    for (int t = 0; t < 3; ++t) {
        uint32_t ab = base + aT[t] + aoff;
        uint32_t bb = base + bT[t] + boff;
        #pragma unroll
        for (int ks = 0; ks < 8; ++ks) {
            uint32_t a0[4], a1[4], b0[4], b1[4];
            ldx4(a0, ab + ks * 32);
            ldx4(a1, ab + 16 * LDT * 2 + ks * 32);
            ldx4(b0, bb + ks * 32);
            ldx4(b1, bb + 16 * LDT * 2 + ks * 32);
            mma16816(acc[0][0], a0, b0[0], b0[1]);
            mma16816(acc[0][1], a0, b0[2], b0[3]);
            mma16816(acc[0][2], a0, b1[0], b1[1]);
            mma16816(acc[0][3], a0, b1[2], b1[3]);
            mma16816(acc[1][0], a1, b0[0], b0[1]);
            mma16816(acc[1][1], a1, b0[2], b0[3]);
            mma16816(acc[1][2], a1, b1[0], b1[1]);
            mma16816(acc[1][3], a1, b1[2], b1[3]);
        }
    }

    float csum[8], csq[8];
    #pragma unroll
    for (int i = 0; i < 8; ++i) { csum[i] = 0.0f; csq[i] = 0.0f; }
    #pragma unroll
    for (int nf = 0; nf < 4; ++nf) {
        int col = nw + nf * 8 + (lane & 3) * 2;
        float bx = __ldg(&bias[col]), by = __ldg(&bias[col + 1]);
        #pragma unroll
        for (int mf = 0; mf < 2; ++mf) {
            int r0 = row0 + mw + mf * 16 + (lane >> 2);
            float v0 = acc[mf][nf][0] + bx, v1 = acc[mf][nf][1] + by;
            float v2 = acc[mf][nf][2] + bx, v3 = acc[mf][nf][3] + by;
            if (r0 < M) {
                *(float2*)&C[(size_t)r0 * DH + col] = make_float2(v0, v1);
                csum[nf * 2] += v0; csum[nf * 2 + 1] += v1;
                csq[nf * 2] += v0 * v0; csq[nf * 2 + 1] += v1 * v1;
            }
            if (r0 + 8 < M) {
                *(float2*)&C[(size_t)(r0 + 8) * DH + col] = make_float2(v2, v3);
                csum[nf * 2] += v2; csum[nf * 2 + 1] += v3;
                csq[nf * 2] += v2 * v2; csq[nf * 2 + 1] += v3 * v3;
            }
        }
    }
    #pragma unroll
    for (int nf = 0; nf < 4; ++nf) {
        int col = nw + nf * 8 + (lane & 3) * 2;
        atomicAdd(&s_sum[col], csum[nf * 2]);
        atomicAdd(&s_sum[col + 1], csum[nf * 2 + 1]);
        atomicAdd(&s_sq[col], csq[nf * 2]);
        atomicAdd(&s_sq[col + 1], csq[nf * 2 + 1]);
    }
    __syncthreads();
    if (tid < 128) {
        atomicAdd(&g_stats[l][1][tid], s_sum[tid]);
        atomicAdd(&g_stats[l][1][128 + tid], s_sq[tid]);
    }
}

// ---------------- per-graph pooling (applies BN+ReLU on the fly) -------
__global__ void pool_kernel(const float* __restrict__ x,
                            const float* __restrict__ go,
                            const float* __restrict__ bo, int M) {
    int g = blockIdx.x, lp = blockIdx.y, c = threadIdx.x;
    int s = g_gstart[g], e = g_gstart[g + 1];
    float acc = 0.0f;
    if (lp == 0) {
        const float* h = x;
        for (int r = s; r < e; ++r) acc += __ldg(&h[(size_t)r * DH + c]);
    } else {
        int l = lp - 1;
        const float* z = &g_zl[l][0];
        float inv = 1.0f / (float)M;
        float m = g_stats[l][1][c] * inv;
        float v = g_stats[l][1][128 + c] * inv - m * m;
        float scl = __ldg(&go[l * DH + c]) * rsqrtf(v + BN_EPS);
        float shf = __ldg(&bo[l * DH + c]) - m * scl;
        for (int r = s; r < e; ++r)
            acc += fmaxf(fmaf(__ldg(&z[(size_t)r * DH + c]), scl, shf), 0.0f);
    }
    g_ph[lp][g * DH + c] = acc;
}

// ---------------- final score: 512 x 64 --------------------------------
__global__ void score_kernel(const float* __restrict__ Wp,
                             const float* __restrict__ bp,
                             float* __restrict__ out) {
    int g = blockIdx.x;
    __shared__ float sph[NL * DH];
    for (int i = threadIdx.x; i < NL * DH; i += blockDim.x) {
        int l = i / DH, c = i % DH;
        sph[i] = g_ph[l][g * DH + c];
    }
    __syncthreads();
    int o = threadIdx.x;  // 64 threads
    float acc = 0.0f;
    for (int l = 0; l < NL; ++l) {
        acc += __ldg(&bp[l * OO + o]);
        const float* Wl = Wp + (size_t)l * DH * OO;
        #pragma unroll 4
        for (int c = 0; c < DH; ++c)
            acc = fmaf(sph[l * DH + c], __ldg(&Wl[c * OO + o]), acc);
    }
    out[g * OO + o] = acc;
}

// ---------------- launcher ---------------------------------------------
extern "C" void kernel_launch(void* const* d_in, const int* in_sizes, int n_in,
                              void* d_out, int out_size) {
    const float* x   = (const float*)d_in[0];
    const int*   src = (const int*)d_in[1];
    const int*   dst = (const int*)d_in[2];
    const int*   gid = (const int*)d_in[3];
    const float* eps = (const float*)d_in[5];
    const float* W1  = (const float*)d_in[6];
    const float* b1  = (const float*)d_in[7];
    const float* gm  = (const float*)d_in[8];
    const float* bm  = (const float*)d_in[9];
    const float* W2  = (const float*)d_in[10];
    const float* b2  = (const float*)d_in[11];
    const float* go  = (const float*)d_in[12];
    const float* bo  = (const float*)d_in[13];
    const float* Wp  = (const float*)d_in[14];
    const float* bp  = (const float*)d_in[15];
    float* out = (float*)d_out;

    int N = in_sizes[0] / DH;   // 100000
    int E = in_sizes[1];        // 1600000

    float *y1, *zl;
    __nv_bfloat16 *whi, *wlo;
    cudaGetSymbolAddress((void**)&y1, g_y1);
    cudaGetSymbolAddress((void**)&zl, g_zl);
    cudaGetSymbolAddress((void**)&whi, g_whi);
    cudaGetSymbolAddress((void**)&wlo, g_wlo);

    static bool attr_done = false;
    if (!attr_done) {
        cudaFuncSetAttribute(fused_agg_gemm1<true>,
                             cudaFuncAttributeMaxDynamicSharedMemorySize, SMEM_BYTES);
        cudaFuncSetAttribute(fused_agg_gemm1<false>,
                             cudaFuncAttributeMaxDynamicSharedMemorySize, SMEM_BYTES);
        cudaFuncSetAttribute(gemm2_mma,
                             cudaFuncAttributeMaxDynamicSharedMemorySize, SMEM_BYTES);
        attr_done = true;
    }

    zero_kernel<<<(N + 255) / 256, 256>>>(N);
    hist_kernel<<<(E + 255) / 256, 256>>>(dst, E);
    scan_kernel<<<1, 1024>>>(N);
    scatter_kernel<<<(E + 255) / 256, 256>>>(src, dst, E);
    gbounds_kernel<<<(N + 1 + 255) / 256, 256>>>(gid, N);
    wconv_kernel<<<(8 * DH * DH + 255) / 256, 256>>>(W1, W2);

    int gemmGrid = (N + 127) / 128;

    for (int l = 0; l < NLG; ++l) {
        float* z_out = zl + (size_t)l * (size_t)NNODES * DH;
        if (l == 0) {
            fused_agg_gemm1<true><<<gemmGrid, 512, SMEM_BYTES>>>(
                x, whi + (size_t)l * DH * DH, wlo + (size_t)l * DH * DH,
                b1 + l * DH, nullptr, nullptr, eps, y1, l, N);
        } else {
            const float* zprev = zl + (size_t)(l - 1) * (size_t)NNODES * DH;
            fused_agg_gemm1<false><<<gemmGrid, 512, SMEM_BYTES>>>(
                zprev, whi + (size_t)l * DH * DH, wlo + (size_t)l * DH * DH,
                b1 + l * DH, go + (l - 1) * DH, bo + (l - 1) * DH, eps, y1, l, N);
        }
        gemm2_mma<<<gemmGrid, 512, SMEM_BYTES>>>(
            y1, whi + (size_t)(4 + l) * DH * DH, wlo + (size_t)(4 + l) * DH * DH,
            b2 + l * DH, gm + l * DH, bm + l * DH, z_out, l, N);
    }

    dim3 pg(NG, NL);
    pool_kernel<<<pg, DH>>>(x, go, bo, N);
    score_kernel<<<NG, 64>>>(Wp, bp, out);
}

// round 5
// speedup vs baseline: 1.2623x; 1.2623x over previous
#include <cuda_runtime.h>
#include <cstdint>

// ---------------- problem constants (fixed by dataset) ----------------
#define NNODES 100000
#define NEDGES 1600000
#define DH 128           // feature dim (D == H)
#define NG 512           // num graphs
#define NL 5             // total reps (input + 4 layers)
#define NLG 4            // GIN layers
#define OO 64            // output dim
#define BN_EPS 1e-5f

// ---------------- static device scratch (no allocations allowed) ------
__device__ float g_zl[NLG][(size_t)NNODES * DH];      // z per GIN layer
__device__ float g_pooled[(size_t)NNODES * DH];
__device__ float g_y1[(size_t)NNODES * DH];
__device__ int   g_deg[NNODES];
__device__ int   g_off[NNODES + 1];
__device__ int   g_cursor[NNODES];
__device__ int   g_srcs[NEDGES];
__device__ int   g_gstart[NG + 1];
__device__ int   g_bsum[128];
__device__ int   g_boff[129];
__device__ int   g_total;
__device__ float g_stats[NLG][2][2 * DH];   // [layer][stage][sum(128)|sumsq(128)]
__device__ float g_ph[NL][NG * DH];         // per-graph pooled reps

// ---------------- small utility kernels --------------------------------
__global__ void zero_kernel(int n_nodes) {
    int i = blockIdx.x * blockDim.x + threadIdx.x;
    if (i < n_nodes) g_deg[i] = 0;
    if (i < NLG * 2 * 2 * DH) ((float*)g_stats)[i] = 0.0f;
}

__global__ void hist_kernel(const int* __restrict__ dst, int E) {
    int i = blockIdx.x * blockDim.x + threadIdx.x;
    if (i < E) atomicAdd(&g_deg[dst[i]], 1);
}

// multi-block scan, step 1: per-block (1024) exclusive scan + block sums
__global__ void scan1_kernel(int n) {
    __shared__ int warpsum[32];
    int tid = threadIdx.x, lane = tid & 31, wid = tid >> 5;
    int i = blockIdx.x * 1024 + tid;
    int v = (i < n) ? g_deg[i] : 0;
    int xv = v;
    #pragma unroll
    for (int o = 1; o < 32; o <<= 1) {
        int t = __shfl_up_sync(0xffffffffu, xv, o);
        if (lane >= o) xv += t;
    }
    if (lane == 31) warpsum[wid] = xv;
    __syncthreads();
    if (wid == 0) {
        int w = warpsum[lane];
        int yv = w;
        #pragma unroll
        for (int o = 1; o < 32; o <<= 1) {
            int t = __shfl_up_sync(0xffffffffu, yv, o);
            if (lane >= o) yv += t;
        }
        warpsum[lane] = yv - w;   // exclusive prefix of warp sums
    }
    __syncthreads();
    int excl = warpsum[wid] + xv - v;     // block-local exclusive
    if (i < n) g_off[i] = excl;
    if (tid == 1023) g_bsum[blockIdx.x] = excl + v;
}

// step 2: single block scans block sums (nb <= 128)
__global__ void scan2_kernel(int nb) {
    __shared__ int s[128];
    int tid = threadIdx.x;
    int v = (tid < nb) ? g_bsum[tid] : 0;
    s[tid] = v;
    __syncthreads();
    #pragma unroll
    for (int o = 1; o < 128; o <<= 1) {
        int t = (tid >= o) ? s[tid - o] : 0;
        __syncthreads();
        s[tid] += t;
        __syncthreads();
    }
    g_boff[tid] = s[tid] - v;             // exclusive
    if (tid == nb - 1) g_total = s[tid];
}

// step 3: add block offsets, copy cursor, set g_off[n]
__global__ void scan3_kernel(int n) {
    int i = blockIdx.x * blockDim.x + threadIdx.x;
    if (i < n) {
        int o = g_off[i] + g_boff[i >> 10];
        g_off[i] = o;
        g_cursor[i] = o;
    }
    if (i == 0) g_off[n] = g_total;
}

__global__ void scatter_kernel(const int* __restrict__ src,
                               const int* __restrict__ dst, int E) {
    int i = blockIdx.x * blockDim.x + threadIdx.x;
    if (i < E) {
        int p = atomicAdd(&g_cursor[dst[i]], 1);
        g_srcs[p] = src[i];
    }
}

__global__ void gbounds_kernel(const int* __restrict__ gid, int n) {
    int i = blockIdx.x * blockDim.x + threadIdx.x;
    if (i > n) return;
    if (i == 0) {
        int b = gid[0];
        for (int g = 0; g <= b; ++g) g_gstart[g] = 0;
    } else if (i == n) {
        int a = gid[n - 1];
        for (int g = a + 1; g <= NG; ++g) g_gstart[g] = n;
    } else {
        int a = gid[i - 1], b = gid[i];
        for (int g = a + 1; g <= b; ++g) g_gstart[g] = i;
    }
}

// ---------------- aggregation: warp per node, CSR gather ---------------
// Reads Hsrc (= x for FIRST, else z of previous layer) and applies
// f = identity (FIRST) or relu(affine) with previous layer's outer-BN
// parameters on the fly; writes pooled = agg(f) + (1+eps)*f(self).
template <bool FIRST>
__global__ void agg_kernel(const float* __restrict__ Hsrc,
                           const float* __restrict__ go_prev,
                           const float* __restrict__ bo_prev,
                           const float* __restrict__ eps, int l, int n) {
    __shared__ float s_sc[128], s_sh[128];
    int tid = threadIdx.x;
    if (!FIRST) {
        if (tid < 128) {
            float inv = 1.0f / (float)n;
            float m = g_stats[l - 1][1][tid] * inv;
            float v = g_stats[l - 1][1][128 + tid] * inv - m * m;
            float s = __ldg(&go_prev[tid]) * rsqrtf(v + BN_EPS);
            s_sc[tid] = s;
            s_sh[tid] = __ldg(&bo_prev[tid]) - m * s;
        }
        __syncthreads();
    }
    int w = (blockIdx.x * blockDim.x + tid) >> 5;
    if (w >= n) return;
    int lane = tid & 31;
    float4 sc = make_float4(1.f, 1.f, 1.f, 1.f);
    float4 sh = make_float4(0.f, 0.f, 0.f, 0.f);
    if (!FIRST) {
        sc = *(float4*)&s_sc[lane * 4];
        sh = *(float4*)&s_sh[lane * 4];
    }
    float onepe = 1.0f + __ldg(&eps[l]);
    const float4* hv = (const float4*)Hsrc;

    float4 vs = __ldg(&hv[(size_t)w * 32 + lane]);
    float4 acc;
    if (!FIRST) {
        vs.x = fmaxf(fmaf(vs.x, sc.x, sh.x), 0.0f);
        vs.y = fmaxf(fmaf(vs.y, sc.y, sh.y), 0.0f);
        vs.z = fmaxf(fmaf(vs.z, sc.z, sh.z), 0.0f);
        vs.w = fmaxf(fmaf(vs.w, sc.w, sh.w), 0.0f);
    }
    acc.x = onepe * vs.x; acc.y = onepe * vs.y;
    acc.z = onepe * vs.z; acc.w = onepe * vs.w;

    int s = g_off[w], e = g_off[w + 1];
    int j = s;
    for (; j + 4 <= e; j += 4) {
        int s0 = g_srcs[j], s1 = g_srcs[j + 1], s2 = g_srcs[j + 2], s3 = g_srcs[j + 3];
        float4 v0 = __ldg(&hv[(size_t)s0 * 32 + lane]);
        float4 v1 = __ldg(&hv[(size_t)s1 * 32 + lane]);
        float4 v2 = __ldg(&hv[(size_t)s2 * 32 + lane]);
        float4 v3 = __ldg(&hv[(size_t)s3 * 32 + lane]);
        if (!FIRST) {
            v0.x = fmaxf(fmaf(v0.x, sc.x, sh.x), 0.0f);
            v0.y = fmaxf(fmaf(v0.y, sc.y, sh.y), 0.0f);
            v0.z = fmaxf(fmaf(v0.z, sc.z, sh.z), 0.0f);
            v0.w = fmaxf(fmaf(v0.w, sc.w, sh.w), 0.0f);
            v1.x = fmaxf(fmaf(v1.x, sc.x, sh.x), 0.0f);
            v1.y = fmaxf(fmaf(v1.y, sc.y, sh.y), 0.0f);
            v1.z = fmaxf(fmaf(v1.z, sc.z, sh.z), 0.0f);
            v1.w = fmaxf(fmaf(v1.w, sc.w, sh.w), 0.0f);
            v2.x = fmaxf(fmaf(v2.x, sc.x, sh.x), 0.0f);
            v2.y = fmaxf(fmaf(v2.y, sc.y, sh.y), 0.0f);
            v2.z = fmaxf(fmaf(v2.z, sc.z, sh.z), 0.0f);
            v2.w = fmaxf(fmaf(v2.w, sc.w, sh.w), 0.0f);
            v3.x = fmaxf(fmaf(v3.x, sc.x, sh.x), 0.0f);
            v3.y = fmaxf(fmaf(v3.y, sc.y, sh.y), 0.0f);
            v3.z = fmaxf(fmaf(v3.z, sc.z, sh.z), 0.0f);
            v3.w = fmaxf(fmaf(v3.w, sc.w, sh.w), 0.0f);
        }
        acc.x += (v0.x + v1.x) + (v2.x + v3.x);
        acc.y += (v0.y + v1.y) + (v2.y + v3.y);
        acc.z += (v0.z + v1.z) + (v2.z + v3.z);
        acc.w += (v0.w + v1.w) + (v2.w + v3.w);
    }
    for (; j < e; ++j) {
        float4 v0 = __ldg(&hv[(size_t)g_srcs[j] * 32 + lane]);
        if (!FIRST) {
            v0.x = fmaxf(fmaf(v0.x, sc.x, sh.x), 0.0f);
            v0.y = fmaxf(fmaf(v0.y, sc.y, sh.y), 0.0f);
            v0.z = fmaxf(fmaf(v0.z, sc.z, sh.z), 0.0f);
            v0.w = fmaxf(fmaf(v0.w, sc.w, sh.w), 0.0f);
        }
        acc.x += v0.x; acc.y += v0.y; acc.z += v0.z; acc.w += v0.w;
    }
    ((float4*)g_pooled)[(size_t)w * 32 + lane] = acc;
}

// ---------------- fused GEMM (+optional pre-BN/ReLU on A, +col stats) --
// C[M,128] = f(A)[M,128] @ W[128,128] + bias ; accumulate col sum/sumsq
template <bool PRE_BN>
__global__ void __launch_bounds__(256, 2)
gemm_kernel(const float* __restrict__ A, const float* __restrict__ W,
            const float* __restrict__ bias,
            const float* __restrict__ gamma, const float* __restrict__ beta,
            float* __restrict__ C, int l, int M) {
    __shared__ float As[8][132];
    __shared__ float Ws[8][128];
    __shared__ float s_scale[128], s_shift[128];
    __shared__ float s_sum[128], s_sq[128];
    int tid = threadIdx.x;
    if (PRE_BN) {
        if (tid < 128) {
            float inv = 1.0f / (float)M;
            float su = g_stats[l][0][tid], sq = g_stats[l][0][128 + tid];
            float m = su * inv;
            float v = sq * inv - m * m;
            float s = __ldg(&gamma[tid]) * rsqrtf(v + BN_EPS);
            s_scale[tid] = s;
            s_shift[tid] = __ldg(&beta[tid]) - m * s;
        }
    }
    if (tid < 128) { s_sum[tid] = 0.0f; s_sq[tid] = 0.0f; }
    __syncthreads();

    int row0 = blockIdx.x * 128;
    int tx = tid & 15, ty = tid >> 4;
    int arow = tid >> 1, acol = (tid & 1) * 4;
    int wrow = tid >> 5, wcol = (tid & 31) * 4;
    int grow = row0 + arow;
    bool aval = (grow < M);
    const float* Aptr = A + (size_t)grow * 128 + acol;
    const float* Wptr = W + (size_t)wrow * 128 + wcol;

    float acc[8][8];
    #pragma unroll
    for (int i = 0; i < 8; ++i)
        #pragma unroll
        for (int j = 0; j < 8; ++j) acc[i][j] = 0.0f;

    for (int kb = 0; kb < 128; kb += 8) {
        float4 av = aval ? *(const float4*)(Aptr + kb) : make_float4(0, 0, 0, 0);
        float4 wv = *(const float4*)(Wptr + (size_t)kb * 128);
        if (PRE_BN && aval) {
            int c = kb + acol;
            av.x = fmaxf(fmaf(av.x, s_scale[c + 0], s_shift[c + 0]), 0.0f);
            av.y = fmaxf(fmaf(av.y, s_scale[c + 1], s_shift[c + 1]), 0.0f);
            av.z = fmaxf(fmaf(av.z, s_scale[c + 2], s_shift[c + 2]), 0.0f);
            av.w = fmaxf(fmaf(av.w, s_scale[c + 3], s_shift[c + 3]), 0.0f);
        }
        __syncthreads();
        As[acol + 0][arow] = av.x;
        As[acol + 1][arow] = av.y;
        As[acol + 2][arow] = av.z;
        As[acol + 3][arow] = av.w;
        *(float4*)&Ws[wrow][wcol] = wv;
        __syncthreads();
        #pragma unroll
        for (int k = 0; k < 8; ++k) {
            float a[8], b[8];
            *(float4*)&a[0] = *(const float4*)&As[k][ty * 8];
            *(float4*)&a[4] = *(const float4*)&As[k][ty * 8 + 4];
            *(float4*)&b[0] = *(const float4*)&Ws[k][tx * 8];
            *(float4*)&b[4] = *(const float4*)&Ws[k][tx * 8 + 4];
            #pragma unroll
            for (int i = 0; i < 8; ++i)
                #pragma unroll
                for (int j = 0; j < 8; ++j)
                    acc[i][j] = fmaf(a[i], b[j], acc[i][j]);
        }
    }

    float bcol[8];
    #pragma unroll
    for (int j = 0; j < 8; ++j) bcol[j] = __ldg(&bias[tx * 8 + j]);
    float psum[8], psq[8];
    #pragma unroll
    for (int j = 0; j < 8; ++j) { psum[j] = 0.0f; psq[j] = 0.0f; }
    #pragma unroll
    for (int i = 0; i < 8; ++i) {
        int gr = row0 + ty * 8 + i;
        if (gr < M) {
            float v[8];
            #pragma unroll
            for (int j = 0; j < 8; ++j) {
                v[j] = acc[i][j] + bcol[j];
                psum[j] += v[j];
                psq[j]  += v[j] * v[j];
            }
            float4 o0 = make_float4(v[0], v[1], v[2], v[3]);
            float4 o1 = make_float4(v[4], v[5], v[6], v[7]);
            *(float4*)&C[(size_t)gr * 128 + tx * 8]     = o0;
            *(float4*)&C[(size_t)gr * 128 + tx * 8 + 4] = o1;
        }
    }
    #pragma unroll
    for (int j = 0; j < 8; ++j) {
        atomicAdd(&s_sum[tx * 8 + j], psum[j]);
        atomicAdd(&s_sq[tx * 8 + j], psq[j]);
    }
    __syncthreads();
    const int stage = PRE_BN ? 1 : 0;
    if (tid < 128) {
        atomicAdd(&g_stats[l][stage][tid], s_sum[tid]);
        atomicAdd(&g_stats[l][stage][128 + tid], s_sq[tid]);
    }
}

// ---------------- per-graph pooling (applies BN+ReLU on the fly) -------
__global__ void pool_kernel(const float* __restrict__ x,
                            const float* __restrict__ go,
                            const float* __restrict__ bo, int M) {
    int g = blockIdx.x, lp = blockIdx.y, c = threadIdx.x;
    int s = g_gstart[g], e = g_gstart[g + 1];
    float acc = 0.0f;
    if (lp == 0) {
        const float* h = x;
        for (int r = s; r < e; ++r) acc += __ldg(&h[(size_t)r * DH + c]);
    } else {
        int l = lp - 1;
        const float* z = &g_zl[l][0];
        float inv = 1.0f / (float)M;
        float m = g_stats[l][1][c] * inv;
        float v = g_stats[l][1][128 + c] * inv - m * m;
        float scl = __ldg(&go[l * DH + c]) * rsqrtf(v + BN_EPS);
        float shf = __ldg(&bo[l * DH + c]) - m * scl;
        for (int r = s; r < e; ++r)
            acc += fmaxf(fmaf(__ldg(&z[(size_t)r * DH + c]), scl, shf), 0.0f);
    }
    g_ph[lp][g * DH + c] = acc;
}

// ---------------- final score: 512 x 64 --------------------------------
__global__ void score_kernel(const float* __restrict__ Wp,
                             const float* __restrict__ bp,
                             float* __restrict__ out) {
    int g = blockIdx.x;
    __shared__ float sph[NL * DH];
    for (int i = threadIdx.x; i < NL * DH; i += blockDim.x) {
        int l = i / DH, c = i % DH;
        sph[i] = g_ph[l][g * DH + c];
    }
    __syncthreads();
    int o = threadIdx.x;  // 64 threads
    float acc = 0.0f;
    for (int l = 0; l < NL; ++l) {
        acc += __ldg(&bp[l * OO + o]);
        const float* Wl = Wp + (size_t)l * DH * OO;
        #pragma unroll 4
        for (int c = 0; c < DH; ++c)
            acc = fmaf(sph[l * DH + c], __ldg(&Wl[c * OO + o]), acc);
    }
    out[g * OO + o] = acc;
}

// ---------------- launcher ---------------------------------------------
extern "C" void kernel_launch(void* const* d_in, const int* in_sizes, int n_in,
                              void* d_out, int out_size) {
    const float* x   = (const float*)d_in[0];
    const int*   src = (const int*)d_in[1];
    const int*   dst = (const int*)d_in[2];
    const int*   gid = (const int*)d_in[3];
    const float* eps = (const float*)d_in[5];
    const float* W1  = (const float*)d_in[6];
    const float* b1  = (const float*)d_in[7];
    const float* gm  = (const float*)d_in[8];
    const float* bm  = (const float*)d_in[9];
    const float* W2  = (const float*)d_in[10];
    const float* b2  = (const float*)d_in[11];
    const float* go  = (const float*)d_in[12];
    const float* bo  = (const float*)d_in[13];
    const float* Wp  = (const float*)d_in[14];
    const float* bp  = (const float*)d_in[15];
    float* out = (float*)d_out;

    int N = in_sizes[0] / DH;   // 100000
    int E = in_sizes[1];        // 1600000

    float *pooled, *y1, *zl;
    cudaGetSymbolAddress((void**)&pooled, g_pooled);
    cudaGetSymbolAddress((void**)&y1, g_y1);
    cudaGetSymbolAddress((void**)&zl, g_zl);

    int nb = (N + 1023) / 1024;

    zero_kernel<<<(N + 255) / 256, 256>>>(N);
    hist_kernel<<<(E + 255) / 256, 256>>>(dst, E);
    scan1_kernel<<<nb, 1024>>>(N);
    scan2_kernel<<<1, 128>>>(nb);
    scan3_kernel<<<(N + 255) / 256, 256>>>(N);
    scatter_kernel<<<(E + 255) / 256, 256>>>(src, dst, E);
    gbounds_kernel<<<(N + 1 + 255) / 256, 256>>>(gid, N);

    int gemmGrid = (N + 127) / 128;
    int aggGrid  = (N * 32 + 255) / 256;  // warp per node

    for (int l = 0; l < NLG; ++l) {
        float* z_out = zl + (size_t)l * (size_t)NNODES * DH;
        if (l == 0) {
            agg_kernel<true><<<aggGrid, 256>>>(x, nullptr, nullptr, eps, l, N);
        } else {
            const float* zprev = zl + (size_t)(l - 1) * (size_t)NNODES * DH;
            agg_kernel<false><<<aggGrid, 256>>>(zprev, go + (l - 1) * DH,
                                                bo + (l - 1) * DH, eps, l, N);
        }
        gemm_kernel<false><<<gemmGrid, 256>>>(pooled, W1 + (size_t)l * DH * DH,
                                              b1 + l * DH, nullptr, nullptr,
                                              y1, l, N);
        gemm_kernel<true><<<gemmGrid, 256>>>(y1, W2 + (size_t)l * DH * DH,
                                             b2 + l * DH, gm + l * DH, bm + l * DH,
                                             z_out, l, N);
    }

    dim3 pg(NG, NL);
    pool_kernel<<<pg, DH>>>(x, go, bo, N);
    score_kernel<<<NG, 64>>>(Wp, bp, out);
}